// round 5
// baseline (speedup 1.0000x reference)
#include <cuda_runtime.h>

#define B_DIM 4
#define T_DIM 1024
#define VD    512
#define HALF  256
#define NL    64
#define C_DIM 256

#define DCHUNK 16                       // d-values per GEMM block
#define NCHUNK (HALF / DCHUNK)          // 16 chunks per label
#define NSLOT  32                       // partial-accumulation slots

// Scratch A[b][l][d] : 256 KB, written exactly once each (no zero-init).
__device__ float g_A[B_DIM * NL * HALF];
// Partial outputs g_P[slot][b][c] : 128 KB (zeroed inside the gather kernel).
__device__ float g_P[NSLOT * B_DIM * C_DIM];

// ---------------------------------------------------------------------------
// Kernel 1: gather + per-label accumulate (ownership model, no atomics).
//   Block (b, l): A[b,l,d] = sum_{t: label[b,t]=l} scores[b,t]*weight[idx,off+d]
// Also zeroes g_P (runs strictly before the GEMM kernel).
// ---------------------------------------------------------------------------
__global__ void vb_gather_kernel(const int*   __restrict__ indices,
                                 const float* __restrict__ scores,
                                 const int*   __restrict__ label,
                                 const int*   __restrict__ index_sel,
                                 const float* __restrict__ weight) {
    __shared__ int   s_idx[T_DIM];
    __shared__ float s_sc [T_DIM];
    __shared__ int   s_cnt;

    const int tid = threadIdx.x;
    const int b   = blockIdx.x / NL;
    const int l   = blockIdx.x % NL;

    // Zero g_P: 32768 floats / 256 blocks = 128 floats per block.
    if (tid < 128) g_P[blockIdx.x * 128 + tid] = 0.0f;
    if (tid == 0) s_cnt = 0;
    __syncthreads();

    #pragma unroll
    for (int j = 0; j < T_DIM / 256; j++) {
        int t = b * T_DIM + j * 256 + tid;
        if (label[t] == l) {
            int pos = atomicAdd(&s_cnt, 1);
            s_idx[pos] = indices[t];
            s_sc [pos] = scores[t];
        }
    }
    __syncthreads();

    const int cnt = s_cnt;
    const int off = (index_sel[0] == 1) ? HALF : 0;
    const int d   = tid;

    float acc = 0.0f;
    int j = 0;
    for (; j + 4 <= cnt; j += 4) {
        float v0 = weight[s_idx[j + 0] * VD + off + d];
        float v1 = weight[s_idx[j + 1] * VD + off + d];
        float v2 = weight[s_idx[j + 2] * VD + off + d];
        float v3 = weight[s_idx[j + 3] * VD + off + d];
        acc += v0 * s_sc[j + 0] + v1 * s_sc[j + 1]
             + v2 * s_sc[j + 2] + v3 * s_sc[j + 3];
    }
    for (; j < cnt; j++)
        acc += weight[s_idx[j] * VD + off + d] * s_sc[j];

    g_A[(b * NL + l) * HALF + d] = acc;   // exclusive write
}

// ---------------------------------------------------------------------------
// Kernel 2: reduction GEMM into partial slots.
//   Block (l, dc): g_P[slot][b][c] += sum_{d in 16-chunk} A[b,l,d]*W[l,off+d,c]
// Grid: NL * NCHUNK = 1024 blocks, 256 threads (thread = c).
// Only 32 blocks collide per slot address -> negligible REDG serialization.
// ---------------------------------------------------------------------------
__global__ void vb_gemm_kernel(const float* __restrict__ W,
                               const int*   __restrict__ index_sel,
                               float*       __restrict__ dummy) {
    const int l    = blockIdx.x / NCHUNK;
    const int dc   = blockIdx.x % NCHUNK;
    const int d0   = dc * DCHUNK;
    const int slot = blockIdx.x & (NSLOT - 1);
    const int c    = threadIdx.x;

    const int off = (index_sel[0] == 1) ? HALF : 0;

    __shared__ float sA[B_DIM][DCHUNK];
    if (threadIdx.x < B_DIM * DCHUNK) {
        int b  = threadIdx.x / DCHUNK;
        int dd = threadIdx.x % DCHUNK;
        sA[b][dd] = g_A[(b * NL + l) * HALF + d0 + dd];
    }
    __syncthreads();

    float acc0 = 0.f, acc1 = 0.f, acc2 = 0.f, acc3 = 0.f;
    const float* Wp = W + ((l * VD) + off + d0) * C_DIM + c;

    #pragma unroll
    for (int d = 0; d < DCHUNK; d++) {
        float w = Wp[d * C_DIM];           // coalesced; 16 independent loads
        acc0 += sA[0][d] * w;
        acc1 += sA[1][d] * w;
        acc2 += sA[2][d] * w;
        acc3 += sA[3][d] * w;
    }

    float* P = g_P + slot * (B_DIM * C_DIM) + c;
    atomicAdd(P + 0 * C_DIM, acc0);
    atomicAdd(P + 1 * C_DIM, acc1);
    atomicAdd(P + 2 * C_DIM, acc2);
    atomicAdd(P + 3 * C_DIM, acc3);
}

// ---------------------------------------------------------------------------
// Kernel 3: final reduce over slots. Grid: B_DIM blocks, 256 threads.
//   out[b,c] = sum_s g_P[s][b][c]   (overwrite; out never needs zeroing)
// ---------------------------------------------------------------------------
__global__ void vb_reduce_kernel(float* __restrict__ out) {
    const int b = blockIdx.x;
    const int c = threadIdx.x;
    float acc = 0.0f;
    #pragma unroll
    for (int s = 0; s < NSLOT; s++)
        acc += g_P[(s * B_DIM + b) * C_DIM + c];
    out[b * C_DIM + c] = acc;
}

// ---------------------------------------------------------------------------
// Launch
// Inputs: indices(i32 B*T), scores(f32 B*T), W(f32 64*512*256),
//   label(i32 B*T), index(i32 scalar), weight(f32 262144*512).
// Output: f32 B*C = 1024.
// ---------------------------------------------------------------------------
extern "C" void kernel_launch(void* const* d_in, const int* in_sizes, int n_in,
                              void* d_out, int out_size) {
    const int*   indices   = (const int*)  d_in[0];
    const float* scores    = (const float*)d_in[1];
    const float* W         = (const float*)d_in[2];
    const int*   label     = (const int*)  d_in[3];
    const int*   index_sel = (const int*)  d_in[4];
    const float* weight    = (const float*)d_in[5];
    float*       out       = (float*)d_out;

    vb_gather_kernel<<<B_DIM * NL, 256>>>(indices, scores, label, index_sel,
                                          weight);
    vb_gemm_kernel<<<NL * NCHUNK, 256>>>(W, index_sel, out);
    vb_reduce_kernel<<<B_DIM, 256>>>(out);
}

// round 7
// speedup vs baseline: 1.1345x; 1.1345x over previous
#include <cuda_runtime.h>

#define B_DIM 4
#define T_DIM 1024
#define VD    512
#define HALF  256
#define NL    64
#define C_DIM 256

#define DCHUNK 32                       // d-values per GEMM block
#define NCHUNK (HALF / DCHUNK)          // 8 chunks per label
#define NSLOT  32                       // partial-accumulation slots

// Scratch A[b][l][d] : 256 KB, written exactly once each (no zero-init).
__device__ float g_A[B_DIM * NL * HALF];
// Partial outputs g_P[slot][b][c] : 128 KB (zeroed inside the gather kernel).
__device__ float g_P[NSLOT * B_DIM * C_DIM];

// ---------------------------------------------------------------------------
// Kernel 1: gather + per-label accumulate (ownership model).
//   Block (b, l): A[b,l,d] = sum_{t: label[b,t]=l} scores[b,t]*weight[idx,off+d]
// 512 threads = 2 token-groups x 256 d-lanes; each group walks alternate
// tokens with 8-way unroll -> up to 16 gather loads in flight per d-lane.
// ---------------------------------------------------------------------------
__global__ void __launch_bounds__(512)
vb_gather_kernel(const int*   __restrict__ indices,
                 const float* __restrict__ scores,
                 const int*   __restrict__ label,
                 const int*   __restrict__ index_sel,
                 const float* __restrict__ weight) {
    __shared__ int   s_idx[T_DIM];
    __shared__ float s_sc [T_DIM];
    __shared__ float s_part[256];
    __shared__ int   s_cnt;

    const int tid = threadIdx.x;
    const int b   = blockIdx.x / NL;
    const int l   = blockIdx.x % NL;

    // Zero g_P: 32768 floats / 256 blocks = 128 floats per block.
    if (tid < 128) g_P[blockIdx.x * 128 + tid] = 0.0f;
    if (tid == 0) s_cnt = 0;
    __syncthreads();

    // Scan this batch row's labels (1024 tokens, 512 threads, 2 iterations).
    #pragma unroll
    for (int j = 0; j < T_DIM / 512; j++) {
        int t = b * T_DIM + j * 512 + tid;
        if (label[t] == l) {
            int pos = atomicAdd(&s_cnt, 1);
            s_idx[pos] = indices[t];
            s_sc [pos] = scores[t];
        }
    }
    __syncthreads();

    const int cnt = s_cnt;
    const int off = (index_sel[0] == 1) ? HALF : 0;
    const int tg  = tid >> 8;      // token group 0/1
    const int d   = tid & 255;

    // This group's tokens: tg, tg+2, tg+4, ...
    const int nj = (cnt - tg + 1) >> 1;          // count for this group
    const float* __restrict__ wbase = weight + off + d;

    float acc = 0.0f;
    int k = 0;
    for (; k + 8 <= nj; k += 8) {
        int j0 = tg + 2 * k;
        float v0 = wbase[(long)s_idx[j0 +  0] * VD];
        float v1 = wbase[(long)s_idx[j0 +  2] * VD];
        float v2 = wbase[(long)s_idx[j0 +  4] * VD];
        float v3 = wbase[(long)s_idx[j0 +  6] * VD];
        float v4 = wbase[(long)s_idx[j0 +  8] * VD];
        float v5 = wbase[(long)s_idx[j0 + 10] * VD];
        float v6 = wbase[(long)s_idx[j0 + 12] * VD];
        float v7 = wbase[(long)s_idx[j0 + 14] * VD];
        acc += v0 * s_sc[j0 +  0] + v1 * s_sc[j0 +  2]
             + v2 * s_sc[j0 +  4] + v3 * s_sc[j0 +  6]
             + v4 * s_sc[j0 +  8] + v5 * s_sc[j0 + 10]
             + v6 * s_sc[j0 + 12] + v7 * s_sc[j0 + 14];
    }
    for (; k < nj; k++) {
        int j = tg + 2 * k;
        acc += wbase[(long)s_idx[j] * VD] * s_sc[j];
    }

    if (tg == 1) s_part[d] = acc;
    __syncthreads();
    if (tg == 0)
        g_A[(b * NL + l) * HALF + d] = acc + s_part[d];   // exclusive write
}

// ---------------------------------------------------------------------------
// Kernel 2: reduction GEMM into partial slots.
//   Block (l, dc): g_P[slot][b][c] += sum_{d in 32-chunk} A[b,l,d]*W[l,off+d,c]
// Grid: NL * NCHUNK = 512 blocks, 256 threads (thread = c).
// 32 coalesced independent W loads in flight per thread.
// ---------------------------------------------------------------------------
__global__ void __launch_bounds__(256)
vb_gemm_kernel(const float* __restrict__ W,
               const int*   __restrict__ index_sel) {
    const int l    = blockIdx.x / NCHUNK;
    const int dc   = blockIdx.x % NCHUNK;
    const int d0   = dc * DCHUNK;
    const int slot = blockIdx.x & (NSLOT - 1);
    const int c    = threadIdx.x;

    const int off = (index_sel[0] == 1) ? HALF : 0;

    __shared__ float sA[B_DIM][DCHUNK];
    if (threadIdx.x < B_DIM * DCHUNK) {
        int b  = threadIdx.x / DCHUNK;
        int dd = threadIdx.x % DCHUNK;
        sA[b][dd] = g_A[(b * NL + l) * HALF + d0 + dd];
    }
    __syncthreads();

    float acc0 = 0.f, acc1 = 0.f, acc2 = 0.f, acc3 = 0.f;
    const float* Wp = W + ((l * VD) + off + d0) * C_DIM + c;

    #pragma unroll
    for (int d = 0; d < DCHUNK; d++) {
        float w = Wp[d * C_DIM];           // coalesced; independent loads
        acc0 += sA[0][d] * w;
        acc1 += sA[1][d] * w;
        acc2 += sA[2][d] * w;
        acc3 += sA[3][d] * w;
    }

    float* P = g_P + slot * (B_DIM * C_DIM) + c;
    atomicAdd(P + 0 * C_DIM, acc0);
    atomicAdd(P + 1 * C_DIM, acc1);
    atomicAdd(P + 2 * C_DIM, acc2);
    atomicAdd(P + 3 * C_DIM, acc3);
}

// ---------------------------------------------------------------------------
// Kernel 3: final reduce over slots. Grid: B_DIM blocks, 256 threads.
// ---------------------------------------------------------------------------
__global__ void vb_reduce_kernel(float* __restrict__ out) {
    const int b = blockIdx.x;
    const int c = threadIdx.x;
    float acc = 0.0f;
    #pragma unroll
    for (int s = 0; s < NSLOT; s++)
        acc += g_P[(s * B_DIM + b) * C_DIM + c];
    out[b * C_DIM + c] = acc;
}

// ---------------------------------------------------------------------------
// Launch
// Inputs: indices(i32 B*T), scores(f32 B*T), W(f32 64*512*256),
//   label(i32 B*T), index(i32 scalar), weight(f32 262144*512).
// Output: f32 B*C = 1024.
// ---------------------------------------------------------------------------
extern "C" void kernel_launch(void* const* d_in, const int* in_sizes, int n_in,
                              void* d_out, int out_size) {
    const int*   indices   = (const int*)  d_in[0];
    const float* scores    = (const float*)d_in[1];
    const float* W         = (const float*)d_in[2];
    const int*   label     = (const int*)  d_in[3];
    const int*   index_sel = (const int*)  d_in[4];
    const float* weight    = (const float*)d_in[5];
    float*       out       = (float*)d_out;

    vb_gather_kernel<<<B_DIM * NL, 512>>>(indices, scores, label, index_sel,
                                          weight);
    vb_gemm_kernel<<<NL * NCHUNK, 256>>>(W, index_sel);
    vb_reduce_kernel<<<B_DIM, 256>>>(out);
}